// round 4
// baseline (speedup 1.0000x reference)
#include <cuda_runtime.h>
#include <cuda_bf16.h>
#include <cstddef>

// Problem constants
#define B_  4
#define C_  256
#define H_  64
#define W_  64
#define P_  (H_*W_)       // 4096
#define COMP_ 64
#define S2_ 4
#define K2_ 25
#define EPS_ 1e-5f
#define MPAD_ 28          // mask row padded to 28 floats (16B-aligned rows)

// Scratch (device globals; no allocation)
__device__ float g_act[B_ * COMP_ * P_];                 // (4,64,64,64)   4.19 MB
__device__ float g_mask2[B_ * S2_ * P_ * MPAD_];         // [b][s][p][28]  7.34 MB

// ---------------------------------------------------------------------------
// Kernel 1: 1x1 compression conv + BatchNorm(eval) + SiLU
// grid (8 pxblocks, 8 outgroups, 4 b), block 256.
// Thread: 2 adjacent pixels (LDG.64) x 8 outputs -> 16 FFMA / ~19 slots.
// ---------------------------------------------------------------------------
__global__ __launch_bounds__(256) void k_compress(
    const float* __restrict__ x, const float* __restrict__ w_comp,
    const float* __restrict__ gamma, const float* __restrict__ beta,
    const float* __restrict__ mean, const float* __restrict__ var)
{
    __shared__ float ws[256][8];    // [c][o_local]
    const int og = blockIdx.y;      // 8 groups of 8 outputs
    const int b  = blockIdx.z;
    const int p  = (blockIdx.x << 9) + threadIdx.x * 2;

    for (int i = threadIdx.x; i < 256 * 8; i += 256) {
        int o = i & 7, c = i >> 3;
        ws[c][o] = w_comp[(og * 8 + o) * 256 + c];
    }
    __syncthreads();

    float acc0[8], acc1[8];
#pragma unroll
    for (int o = 0; o < 8; o++) { acc0[o] = 0.f; acc1[o] = 0.f; }

    const float2* xb = (const float2*)(x + ((size_t)b * C_) * P_ + p);
#pragma unroll 8
    for (int c = 0; c < 256; c++) {
        float2 xv = xb[(size_t)c * (P_ / 2)];
        float4 w0 = *(const float4*)&ws[c][0];
        float4 w1 = *(const float4*)&ws[c][4];
        acc0[0] += w0.x * xv.x; acc1[0] += w0.x * xv.y;
        acc0[1] += w0.y * xv.x; acc1[1] += w0.y * xv.y;
        acc0[2] += w0.z * xv.x; acc1[2] += w0.z * xv.y;
        acc0[3] += w0.w * xv.x; acc1[3] += w0.w * xv.y;
        acc0[4] += w1.x * xv.x; acc1[4] += w1.x * xv.y;
        acc0[5] += w1.y * xv.x; acc1[5] += w1.y * xv.y;
        acc0[6] += w1.z * xv.x; acc1[6] += w1.z * xv.y;
        acc0[7] += w1.w * xv.x; acc1[7] += w1.w * xv.y;
    }

#pragma unroll
    for (int o = 0; o < 8; o++) {
        int oc = og * 8 + o;
        float sc = gamma[oc] * rsqrtf(var[oc] + EPS_);
        float mu = mean[oc], bt = beta[oc];
        float v0 = (acc0[o] - mu) * sc + bt;
        float v1 = (acc1[o] - mu) * sc + bt;
        float a0 = v0 / (1.f + __expf(-v0));
        float a1 = v1 / (1.f + __expf(-v1));
        *(float2*)&g_act[((size_t)b * COMP_ + oc) * P_ + p] = make_float2(a0, a1);
    }
}

// ---------------------------------------------------------------------------
// Kernel 2: 3x3 encoder conv (64->25 per s-slice) + softmax over k (25)
// grid (16 tiles, 4 s, 4 b), block 128. Tile 16x16 px, 2 adjacent px/thread.
// Two ci passes (32+32) keep smem ~80KB -> 2 blocks/SM.
// ---------------------------------------------------------------------------
#define ENC_ACT_FLOATS (32 * 18 * 18)        // 10368
#define ENC_W_FLOATS   (25 * 32 * 12)        // 9600 (rows padded 9->12)
#define ENC_SMEM_BYTES ((ENC_ACT_FLOATS + ENC_W_FLOATS) * 4)   // 79872

__global__ __launch_bounds__(128) void k_encoder(const float* __restrict__ w_enc)
{
    extern __shared__ float sm[];
    float* act_s = sm;                      // [cl][yy][xx] pitch 18 (32 ch)
    float* w_s   = sm + ENC_ACT_FLOATS;     // [k][cl][12]

    const int s = blockIdx.y;
    const int b = blockIdx.z;
    const int tile = blockIdx.x;
    const int ty0 = (tile >> 2) * 16, tx0 = (tile & 3) * 16;
    const int tid = threadIdx.x;
    const int py = tid >> 3;                // 0..15
    const int pxp = tid & 7;                // pixel pair: px = 2*pxp, 2*pxp+1

    float acc0[25], acc1[25];
#pragma unroll
    for (int k = 0; k < 25; k++) { acc0[k] = 0.f; acc1[k] = 0.f; }

    for (int pass = 0; pass < 2; pass++) {
        if (pass) __syncthreads();
        const int ci0 = pass * 32;

        for (int i = tid; i < 25 * 288; i += 128) {
            int k = i / 288, rem = i % 288;
            int cl = rem / 9, q = rem % 9;
            w_s[k * 384 + cl * 12 + q] = w_enc[(k * 4 + s) * 576 + (ci0 + cl) * 9 + q];
        }
        for (int i = tid; i < ENC_ACT_FLOATS; i += 128) {
            int cl = i / 324, r = i % 324;
            int yy = r / 18, xx = r % 18;
            int gy = ty0 + yy - 1, gx = tx0 + xx - 1;
            float v = 0.f;
            if ((unsigned)gy < 64u && (unsigned)gx < 64u)
                v = g_act[((size_t)b * COMP_ + ci0 + cl) * P_ + gy * 64 + gx];
            act_s[i] = v;
        }
        __syncthreads();

        for (int cl = 0; cl < 32; cl++) {
            // 3x4 activation window covering both pixels of the pair
            float a[12];
            const float* ap = act_s + cl * 324 + py * 18 + 2 * pxp;
#pragma unroll
            for (int dy = 0; dy < 3; dy++)
#pragma unroll
                for (int dx = 0; dx < 4; dx++)
                    a[dy * 4 + dx] = ap[dy * 18 + dx];

            const float4* wbase = (const float4*)(w_s + cl * 12);
#pragma unroll
            for (int k = 0; k < 25; k++) {
                const float4* wk = wbase + k * 96;   // k*384 floats /4
                float4 w0 = wk[0], w1 = wk[1], w2 = wk[2];
                acc0[k] += w0.x * a[0] + w0.y * a[1] + w0.z * a[2]
                         + w0.w * a[4] + w1.x * a[5] + w1.y * a[6]
                         + w1.z * a[8] + w1.w * a[9] + w2.x * a[10];
                acc1[k] += w0.x * a[1] + w0.y * a[2] + w0.z * a[3]
                         + w0.w * a[5] + w1.x * a[6] + w1.y * a[7]
                         + w1.z * a[9] + w1.w * a[10] + w2.x * a[11];
            }
        }
    }

    // softmax over 25 for each pixel
    float m0 = acc0[0], m1 = acc1[0];
#pragma unroll
    for (int k = 1; k < 25; k++) { m0 = fmaxf(m0, acc0[k]); m1 = fmaxf(m1, acc1[k]); }
    float s0 = 0.f, s1 = 0.f;
#pragma unroll
    for (int k = 0; k < 25; k++) {
        acc0[k] = __expf(acc0[k] - m0); s0 += acc0[k];
        acc1[k] = __expf(acc1[k] - m1); s1 += acc1[k];
    }
    float i0 = 1.f / s0, i1 = 1.f / s1;
#pragma unroll
    for (int k = 0; k < 25; k++) { acc0[k] *= i0; acc1[k] *= i1; }

    const int gp = (ty0 + py) * 64 + tx0 + 2 * pxp;
    float4* mp0 = (float4*)(g_mask2 + (((size_t)b * S2_ + s) * P_ + gp) * MPAD_);
    float4* mp1 = (float4*)(g_mask2 + (((size_t)b * S2_ + s) * P_ + gp + 1) * MPAD_);
    mp0[0] = make_float4(acc0[0],  acc0[1],  acc0[2],  acc0[3]);
    mp0[1] = make_float4(acc0[4],  acc0[5],  acc0[6],  acc0[7]);
    mp0[2] = make_float4(acc0[8],  acc0[9],  acc0[10], acc0[11]);
    mp0[3] = make_float4(acc0[12], acc0[13], acc0[14], acc0[15]);
    mp0[4] = make_float4(acc0[16], acc0[17], acc0[18], acc0[19]);
    mp0[5] = make_float4(acc0[20], acc0[21], acc0[22], acc0[23]);
    mp0[6] = make_float4(acc0[24], 0.f, 0.f, 0.f);
    mp1[0] = make_float4(acc1[0],  acc1[1],  acc1[2],  acc1[3]);
    mp1[1] = make_float4(acc1[4],  acc1[5],  acc1[6],  acc1[7]);
    mp1[2] = make_float4(acc1[8],  acc1[9],  acc1[10], acc1[11]);
    mp1[3] = make_float4(acc1[12], acc1[13], acc1[14], acc1[15]);
    mp1[4] = make_float4(acc1[16], acc1[17], acc1[18], acc1[19]);
    mp1[5] = make_float4(acc1[20], acc1[21], acc1[22], acc1[23]);
    mp1[6] = make_float4(acc1[24], 0.f, 0.f, 0.f);
}

// ---------------------------------------------------------------------------
// Kernel 3: content-aware reassembly + pixel shuffle
// grid (64 tiles of 8x8, 8 cgroups of 32, 4 b), block 256 =
//   64 px * 2 csub * 2 sgrp. Thread: 16 channels, 2 s values (50 mask regs —
//   no spills under the 128-reg cap).
// ---------------------------------------------------------------------------
__global__ __launch_bounds__(256, 2) void k_reassemble(
    const float* __restrict__ x, float* __restrict__ out)
{
    __shared__ float xs[32][144];        // [c_local][12x12]   18.4KB
    __shared__ float ms[256][MPAD_];     // [(s*64+px)][k]     28.7KB

    const int b = blockIdx.z;
    const int cg = blockIdx.y;
    const int tile = blockIdx.x;
    const int ty0 = (tile >> 3) * 8, tx0 = (tile & 7) * 8;
    const int tid = threadIdx.x;

    // x tile (halo 2, zero pad)
    for (int i = tid; i < 32 * 144; i += 256) {
        int cl = i / 144, r = i % 144;
        int yy = r / 12, xx = r % 12;
        int gy = ty0 + yy - 2, gx = tx0 + xx - 2;
        float v = 0.f;
        if ((unsigned)gy < 64u && (unsigned)gx < 64u)
            v = x[(((size_t)b * C_ + cg * 32 + cl) * 64 + gy) * 64 + gx];
        xs[cl][r] = v;
    }
    // mask tile: 256 rows x 7 float4 (L2-resident)
    for (int i = tid; i < 256 * 7; i += 256) {
        int row = i / 7, j = i % 7;
        int s = row >> 6, px = row & 63;
        int gp = (ty0 + (px >> 3)) * 64 + tx0 + (px & 7);
        const float4* src = (const float4*)(g_mask2 + (((size_t)b * S2_ + s) * P_ + gp) * MPAD_);
        *((float4*)ms[row] + j) = src[j];
    }
    __syncthreads();

    const int sgrp = tid >> 7;            // s0 (output row parity)
    const int csub = (tid >> 6) & 1;      // 16-channel half
    const int px   = tid & 63;
    const int py = px >> 3, pxl = px & 7;

    // cache 50 mask values (2 s) in registers
    float mk0[25], mk1[25];
#pragma unroll
    for (int k = 0; k < 25; k++) {
        mk0[k] = ms[(sgrp * 2 + 0) * 64 + px][k];
        mk1[k] = ms[(sgrp * 2 + 1) * 64 + px][k];
    }

    const int gy = ty0 + py, gx = tx0 + pxl;
    const size_t row_base = (((size_t)b * C_ + cg * 32) * 128 + 2 * gy + sgrp) * 128 + 2 * gx;

#pragma unroll
    for (int cc = 0; cc < 16; cc++) {
        int cl = csub * 16 + cc;
        float xr[25];
#pragma unroll
        for (int dy = 0; dy < 5; dy++)
#pragma unroll
            for (int dx = 0; dx < 5; dx++)
                xr[dy * 5 + dx] = xs[cl][(py + dy) * 12 + pxl + dx];

        float a0 = 0.f, a1 = 0.f;
#pragma unroll
        for (int k = 0; k < 25; k++) {
            a0 += mk0[k] * xr[k];
            a1 += mk1[k] * xr[k];
        }

        *(float2*)(out + row_base + (size_t)cl * 128 * 128) = make_float2(a0, a1);
    }
}

// ---------------------------------------------------------------------------
extern "C" void kernel_launch(void* const* d_in, const int* in_sizes, int n_in,
                              void* d_out, int out_size)
{
    const float* x       = (const float*)d_in[0];
    const float* w_comp  = (const float*)d_in[1];
    const float* bn_g    = (const float*)d_in[2];
    const float* bn_b    = (const float*)d_in[3];
    const float* bn_m    = (const float*)d_in[4];
    const float* bn_v    = (const float*)d_in[5];
    const float* w_enc   = (const float*)d_in[6];
    float* out = (float*)d_out;

    cudaFuncSetAttribute(k_encoder, cudaFuncAttributeMaxDynamicSharedMemorySize,
                         ENC_SMEM_BYTES);

    dim3 g1(8, 8, B_);
    k_compress<<<g1, 256>>>(x, w_comp, bn_g, bn_b, bn_m, bn_v);

    dim3 g2(16, 4, B_);
    k_encoder<<<g2, 128, ENC_SMEM_BYTES>>>(w_enc);

    dim3 g3(64, 8, B_);
    k_reassemble<<<g3, 256>>>(x, out);
}